// round 10
// baseline (speedup 1.0000x reference)
#include <cuda_runtime.h>
#include <math.h>

#define B_  512
#define T_  24
#define V_  8000
#define E_  300
#define M_  30
#define H_  330
#define HP  352            // padded H (11 warps)
#define NSTEPS 8
#define DT_ 0.875f         // 7/8
#define VP  8192           // padded V for W_d2T
#define NP1 320            // padded N for d1 stage

// ---------------- device scratch (static, no allocation) ----------------
__device__ float g_WodeT[3 * HP * HP];   // [which][k][n] k<330 real, zero-padded
__device__ float g_WuT[HP * HP];         // [k<330][n<300]
__device__ float g_WihT[E_ * 96];        // [e<300][g<90]
__device__ float g_WhhT[M_ * 96];        // [m<30][g<90]
__device__ float g_Wd1T[E_ * NP1];       // [k<300][n<300]
__device__ float g_Wd2T[E_ * VP];        // [n<300][v<8000]
__device__ float g_WembT[V_ * E_];       // [v][e]
__device__ float g_bu_pad[HP];
__device__ float g_bd1_pad[NP1];
__device__ int   g_len[B_];
__device__ float g_gall[(size_t)B_ * T_ * E_];        // [b][t][e]
__device__ float g_hemb[(size_t)(T_ - 1) * B_ * E_];  // [kk][b][e]
__device__ float g_d1[(size_t)(T_ - 1) * B_ * E_];    // [kk][b][e]

// ---------------- lengths normalization (int32 vs int64 auto-detect) ----------------
// Reference builds lengths with .astype(jnp.int64); under default JAX x64-disabled
// that is int32. lengths >= 2 always, so viewing the buffer as int32:
//   int64 data  -> word[1] is the high word of lengths[0] == 0
//   int32 data  -> word[1] == lengths[1] in [2,24] != 0
__global__ void prep_len(const int* __restrict__ Lraw) {
    int b = blockIdx.x * blockDim.x + threadIdx.x;
    if (b >= B_) return;
    int is64 = (Lraw[1] == 0);
    g_len[b] = is64 ? Lraw[2 * b] : Lraw[b];
}

// ---------------- weight prep ----------------
__global__ void prep_ode(const float* __restrict__ W1, const float* __restrict__ W2,
                         const float* __restrict__ W3) {
    int i = blockIdx.x * blockDim.x + threadIdx.x;
    if (i >= HP * HP) return;
    int k = i / HP, n = i % HP;
    float v1 = 0.f, v2 = 0.f, v3 = 0.f;
    if (k < H_ && n < H_) {
        v1 = W1[n * H_ + k];
        v2 = W2[n * H_ + k];
        v3 = W3[n * H_ + k];
    }
    g_WodeT[i] = v1;
    g_WodeT[HP * HP + i] = v2;
    g_WodeT[2 * HP * HP + i] = v3;
}

__global__ void prep_misc(const float* __restrict__ Wu,  const float* __restrict__ bu,
                          const float* __restrict__ Wih, const float* __restrict__ Whh,
                          const float* __restrict__ Wd1, const float* __restrict__ bd1) {
    int i = blockIdx.x * blockDim.x + threadIdx.x;
    if (i < HP * HP) {
        int k = i / HP, n = i % HP;
        g_WuT[i] = (k < H_ && n < E_) ? Wu[n * H_ + k] : 0.f;
    }
    if (i < E_ * 96) {
        int e = i / 96, g = i % 96;
        g_WihT[i] = (g < 90) ? Wih[g * E_ + e] : 0.f;
    }
    if (i < M_ * 96) {
        int m = i / 96, g = i % 96;
        g_WhhT[i] = (g < 90) ? Whh[g * M_ + m] : 0.f;
    }
    if (i < E_ * NP1) {
        int k = i / NP1, n = i % NP1;
        g_Wd1T[i] = (n < E_) ? Wd1[n * E_ + k] : 0.f;
    }
    if (i < HP)  g_bu_pad[i]  = (i < E_) ? bu[i]  : 0.f;
    if (i < NP1) g_bd1_pad[i] = (i < E_) ? bd1[i] : 0.f;
}

__global__ void prep_wd2(const float* __restrict__ Wd2) {
    int i = blockIdx.x * blockDim.x + threadIdx.x;
    if (i >= E_ * VP) return;
    int n = i / VP, v = i % VP;
    g_Wd2T[i] = (v < V_) ? Wd2[v * E_ + n] : 0.f;
}

__global__ void prep_wemb(const float* __restrict__ Wemb) {
    int i = blockIdx.x * blockDim.x + threadIdx.x;
    if (i >= V_ * E_) return;
    int v = i / E_, e = i % E_;
    g_WembT[i] = Wemb[e * V_ + v];
}

// ---------------- sparse embedding: g_all = codes @ W_emb^T + b_emb ----------------
// Deterministic compaction: prefix-scan ordered gather (no atomics) so every call
// produces bit-identical output.
__global__ void __launch_bounds__(256) embed_kernel(const float* __restrict__ codes,
                                                    const float* __restrict__ bemb) {
    __shared__ int idx[1024];
    __shared__ int cnts[256];
    __shared__ int total;
    int blk = blockIdx.x;               // blk = b*T_ + t
    int t = threadIdx.x;
    const float* crow = codes + (size_t)blk * V_;
    int base = t * 32;
    int c = 0;
#pragma unroll 4
    for (int j = 0; j < 32; j++) {
        int v = base + j;
        if (v < V_ && crow[v] != 0.f) c++;
    }
    cnts[t] = c;
    __syncthreads();
    // inclusive scan over 256 counts
    for (int off = 1; off < 256; off <<= 1) {
        int val = cnts[t];
        int add = (t >= off) ? cnts[t - off] : 0;
        __syncthreads();
        cnts[t] = val + add;
        __syncthreads();
    }
    int p = cnts[t] - c;                // exclusive start
    for (int j = 0; j < 32; j++) {
        int v = base + j;
        if (v < V_ && crow[v] != 0.f) {
            if (p < 1024) idx[p] = v;
            p++;
        }
    }
    if (t == 255) total = cnts[255];
    __syncthreads();
    int n = total > 1024 ? 1024 : total;
    for (int e = t; e < E_; e += 256) {
        float acc = bemb[e];
        for (int j = 0; j < n; j++) acc += g_WembT[idx[j] * E_ + e];
        g_gall[(size_t)blk * E_ + e] = acc;
    }
}

// ---------------- sequential ODE + GRU kernel ----------------
// Activations in smem stored k-major as float4 over 4 batch rows.
template <bool TANH, bool BIAS>
__device__ __forceinline__ void mm_stage(const float* __restrict__ WT,
                                         const float4* __restrict__ xs,
                                         float4* __restrict__ ys,
                                         const float* __restrict__ bias, int tid) {
    float a0, a1, a2, a3;
    if (BIAS) { float bv = bias[tid]; a0 = a1 = a2 = a3 = bv; }
    else      { a0 = a1 = a2 = a3 = 0.f; }
    const float* wp = WT + tid;
#pragma unroll 6
    for (int k = 0; k < H_; k++) {
        float w = wp[k * HP];
        float4 x = xs[k];
        a0 = fmaf(w, x.x, a0);
        a1 = fmaf(w, x.y, a1);
        a2 = fmaf(w, x.z, a2);
        a3 = fmaf(w, x.w, a3);
    }
    if (TANH) { a0 = tanhf(a0); a1 = tanhf(a1); a2 = tanhf(a2); a3 = tanhf(a3); }
    ys[tid] = make_float4(a0, a1, a2, a3);
    __syncthreads();
}

__device__ __forceinline__ void ode_f(const float4* src, float4* bufA, float4* bufB, int tid) {
    mm_stage<true, false>(g_WodeT,               src,  bufA, nullptr, tid);  // W1
    mm_stage<true, false>(g_WodeT + HP * HP,     bufA, bufB, nullptr, tid);  // W2
    mm_stage<true, false>(g_WodeT + 2 * HP * HP, bufB, bufA, nullptr, tid);  // W3 -> bufA
}

__device__ __forceinline__ float sigf(float x) { return 1.f / (1.f + expf(-x)); }

__global__ void __launch_bounds__(HP, 1) seq_kernel(const float* __restrict__ b_ih,
                                                    const float* __restrict__ b_hh) {
    __shared__ float4 Hs[HP], ACC[HP], Ys[HP], As[HP], Bs[HP];
    __shared__ float4 G1[96], G2[96];
    int tid = threadIdx.x;
    int b0 = blockIdx.x * 4;

    // h0 = [zeros(M), g_all[:,0,:]]
    {
        float4 h = make_float4(0.f, 0.f, 0.f, 0.f);
        if (tid >= M_ && tid < H_) {
            int e = tid - M_;
            h.x = g_gall[((size_t)(b0 + 0) * T_ + 0) * E_ + e];
            h.y = g_gall[((size_t)(b0 + 1) * T_ + 0) * E_ + e];
            h.z = g_gall[((size_t)(b0 + 2) * T_ + 0) * E_ + e];
            h.w = g_gall[((size_t)(b0 + 3) * T_ + 0) * E_ + e];
        }
        Hs[tid] = h;
        __syncthreads();
    }

    for (int k = 1; k < T_; k++) {
        // ---- RK4 with N_STEPS substeps ----
        for (int s = 0; s < NSTEPS; s++) {
            ode_f(Hs, As, Bs, tid);                              // k1 -> As
            {
                float4 a = As[tid], h = Hs[tid];
                ACC[tid] = a;
                Ys[tid] = make_float4(h.x + 0.5f * DT_ * a.x, h.y + 0.5f * DT_ * a.y,
                                      h.z + 0.5f * DT_ * a.z, h.w + 0.5f * DT_ * a.w);
                __syncthreads();
            }
            ode_f(Ys, As, Bs, tid);                              // k2 -> As
            {
                float4 a = As[tid], h = Hs[tid], c = ACC[tid];
                ACC[tid] = make_float4(c.x + 2.f * a.x, c.y + 2.f * a.y,
                                       c.z + 2.f * a.z, c.w + 2.f * a.w);
                Ys[tid] = make_float4(h.x + 0.5f * DT_ * a.x, h.y + 0.5f * DT_ * a.y,
                                      h.z + 0.5f * DT_ * a.z, h.w + 0.5f * DT_ * a.w);
                __syncthreads();
            }
            ode_f(Ys, As, Bs, tid);                              // k3 -> As
            {
                float4 a = As[tid], h = Hs[tid], c = ACC[tid];
                ACC[tid] = make_float4(c.x + 2.f * a.x, c.y + 2.f * a.y,
                                       c.z + 2.f * a.z, c.w + 2.f * a.w);
                Ys[tid] = make_float4(h.x + DT_ * a.x, h.y + DT_ * a.y,
                                      h.z + DT_ * a.z, h.w + DT_ * a.w);
                __syncthreads();
            }
            ode_f(Ys, As, Bs, tid);                              // k4 -> As
            {
                const float c6 = DT_ / 6.f;
                float4 a = As[tid], h = Hs[tid], c = ACC[tid];
                Hs[tid] = make_float4(h.x + c6 * (c.x + a.x), h.y + c6 * (c.y + a.y),
                                      h.z + c6 * (c.z + a.z), h.w + c6 * (c.w + a.w));
                __syncthreads();
            }
        }

        // ---- dump h_emb for the decoupled decoder; build cin = [h_mem, g_k] ----
        if (tid < E_) {
            float4 v = Hs[M_ + tid];
            size_t base = ((size_t)(k - 1) * B_ + b0) * E_ + tid;
            g_hemb[base]          = v.x;
            g_hemb[base + E_]     = v.y;
            g_hemb[base + 2 * E_] = v.z;
            g_hemb[base + 3 * E_] = v.w;
        }
        {
            float4 c = make_float4(0.f, 0.f, 0.f, 0.f);
            if (tid < M_) c = Hs[tid];
            else if (tid < H_) {
                int e = tid - M_;
                c.x = g_gall[((size_t)(b0 + 0) * T_ + k) * E_ + e];
                c.y = g_gall[((size_t)(b0 + 1) * T_ + k) * E_ + e];
                c.z = g_gall[((size_t)(b0 + 2) * T_ + k) * E_ + e];
                c.w = g_gall[((size_t)(b0 + 3) * T_ + k) * E_ + e];
            }
            Ys[tid] = c;
            __syncthreads();
        }

        // ---- x = cin @ W_u^T + b_u  -> As ----
        mm_stage<false, true>(g_WuT, Ys, As, g_bu_pad, tid);

        // ---- GRU gates ----
        if (tid < 96) {
            int g = tid;
            float bb = (g < 90) ? b_ih[g] : 0.f;
            float4 a = make_float4(bb, bb, bb, bb);
#pragma unroll 4
            for (int e = 0; e < E_; e++) {
                float w = g_WihT[e * 96 + g];
                float4 x = As[e];
                a.x = fmaf(w, x.x, a.x); a.y = fmaf(w, x.y, a.y);
                a.z = fmaf(w, x.z, a.z); a.w = fmaf(w, x.w, a.w);
            }
            G1[g] = a;
        } else if (tid < 192) {
            int g = tid - 96;
            float bb = (g < 90) ? b_hh[g] : 0.f;
            float4 a = make_float4(bb, bb, bb, bb);
#pragma unroll
            for (int m = 0; m < M_; m++) {
                float w = g_WhhT[m * 96 + g];
                float4 x = Hs[m];
                a.x = fmaf(w, x.x, a.x); a.y = fmaf(w, x.y, a.y);
                a.z = fmaf(w, x.z, a.z); a.w = fmaf(w, x.w, a.w);
            }
            G2[g] = a;
        }
        __syncthreads();

        if (tid < M_) {
            int m = tid;
            float4 xr = G1[m],          hr = G2[m];
            float4 xz = G1[M_ + m],     hz = G2[M_ + m];
            float4 xn = G1[2 * M_ + m], hn = G2[2 * M_ + m];
            float4 ho = Hs[m];
            float4 hnew;
            {
                float r = sigf(xr.x + hr.x), z = sigf(xz.x + hz.x);
                float n = tanhf(xn.x + r * hn.x);
                hnew.x = (1.f - z) * n + z * ho.x;
            }
            {
                float r = sigf(xr.y + hr.y), z = sigf(xz.y + hz.y);
                float n = tanhf(xn.y + r * hn.y);
                hnew.y = (1.f - z) * n + z * ho.y;
            }
            {
                float r = sigf(xr.z + hr.z), z = sigf(xz.z + hz.z);
                float n = tanhf(xn.z + r * hn.z);
                hnew.z = (1.f - z) * n + z * ho.z;
            }
            {
                float r = sigf(xr.w + hr.w), z = sigf(xz.w + hz.w);
                float n = tanhf(xn.w + r * hn.w);
                hnew.w = (1.f - z) * n + z * ho.w;
            }
            Hs[m] = hnew;
        }
        __syncthreads();
    }
}

// ---------------- decoder stage 1: d1 = leaky_relu(hemb @ W_d1^T + b_d1) ----------------
__global__ void __launch_bounds__(NP1) d1_kernel() {
    __shared__ float4 Xs[E_];
    int tid = threadIdx.x;
    int i0 = blockIdx.x * 4;
    if (tid < E_) {
        float4 v;
        v.x = g_hemb[(size_t)(i0 + 0) * E_ + tid];
        v.y = g_hemb[(size_t)(i0 + 1) * E_ + tid];
        v.z = g_hemb[(size_t)(i0 + 2) * E_ + tid];
        v.w = g_hemb[(size_t)(i0 + 3) * E_ + tid];
        Xs[tid] = v;
    }
    __syncthreads();
    int n = tid;
    float bv = g_bd1_pad[n];
    float a0 = bv, a1 = bv, a2 = bv, a3 = bv;
#pragma unroll 5
    for (int kk = 0; kk < E_; kk++) {
        float w = g_Wd1T[kk * NP1 + n];
        float4 x = Xs[kk];
        a0 = fmaf(w, x.x, a0); a1 = fmaf(w, x.y, a1);
        a2 = fmaf(w, x.z, a2); a3 = fmaf(w, x.w, a3);
    }
    a0 = a0 >= 0.f ? a0 : 0.01f * a0;
    a1 = a1 >= 0.f ? a1 : 0.01f * a1;
    a2 = a2 >= 0.f ? a2 : 0.01f * a2;
    a3 = a3 >= 0.f ? a3 : 0.01f * a3;
    if (n < E_) {
        g_d1[(size_t)(i0 + 0) * E_ + n] = a0;
        g_d1[(size_t)(i0 + 1) * E_ + n] = a1;
        g_d1[(size_t)(i0 + 2) * E_ + n] = a2;
        g_d1[(size_t)(i0 + 3) * E_ + n] = a3;
    }
}

// ---------------- decoder stage 2: logits = d1 @ W_d2^T + b_d2 (masked) ----------------
#define AS4 9   // A_s row stride in float4 (36 floats)
__global__ void __launch_bounds__(256) logits_kernel(const float* __restrict__ bd2,
                                                     float* __restrict__ out) {
    __shared__ float4 A_s4[E_ * AS4];
    __shared__ int vld[32];
    float* A_s = (float*)A_s4;
    int tid = threadIdx.x;
    int i0 = blockIdx.x * 32;                 // row tile (i = kk*512 + b)
    int vt = blockIdx.y * 256;                // v tile

    if (tid < 32) {
        int i = i0 + tid;
        int kk = i >> 9, b = i & 511;
        vld[tid] = ((kk + 1) < g_len[b]) ? 1 : 0;
    }
    int any = __syncthreads_or(
        tid < 32 ? ((((i0 + tid) >> 9) + 1) < g_len[(i0 + tid) & 511]) : 0);

    int vq = vt + (tid & 63) * 4;
    int g2 = (tid >> 6) * 2;                  // float4 offset within A_s row
    int rb = (tid >> 6) * 8;                  // first of 8 rows this thread owns
    float4 acc[8];
#pragma unroll
    for (int r = 0; r < 8; r++) acc[r] = make_float4(0.f, 0.f, 0.f, 0.f);

    if (any) {
        for (int idx = tid; idx < 32 * E_; idx += 256) {
            int r = idx / E_, kk = idx - r * E_;
            A_s[kk * 36 + r] = g_d1[(size_t)(i0 + r) * E_ + kk];
        }
        __syncthreads();
        if (vq < V_) {
#pragma unroll 2
            for (int kk = 0; kk < E_; kk++) {
                float4 w = *(const float4*)&g_Wd2T[(size_t)kk * VP + vq];
                float4 xa = A_s4[kk * AS4 + g2];
                float4 xb = A_s4[kk * AS4 + g2 + 1];
                float ar[8] = {xa.x, xa.y, xa.z, xa.w, xb.x, xb.y, xb.z, xb.w};
#pragma unroll
                for (int r = 0; r < 8; r++) {
                    acc[r].x = fmaf(ar[r], w.x, acc[r].x);
                    acc[r].y = fmaf(ar[r], w.y, acc[r].y);
                    acc[r].z = fmaf(ar[r], w.z, acc[r].z);
                    acc[r].w = fmaf(ar[r], w.w, acc[r].w);
                }
            }
        }
    }

    if (vq < V_) {
        float4 bb = *(const float4*)&bd2[vq];
        const float4 zero = make_float4(0.f, 0.f, 0.f, 0.f);
#pragma unroll
        for (int r = 0; r < 8; r++) {
            int i = i0 + rb + r;
            int kk = i >> 9, b = i & 511;
            float4 o;
            if (vld[rb + r]) {
                o = make_float4(acc[r].x + bb.x, acc[r].y + bb.y,
                                acc[r].z + bb.z, acc[r].w + bb.w);
            } else {
                o = zero;
            }
            *(float4*)&out[((size_t)b * (T_ - 1) + kk) * V_ + vq] = o;
        }
    }
}

// ---------------- launch ----------------
extern "C" void kernel_launch(void* const* d_in, const int* in_sizes, int n_in,
                              void* d_out, int out_size) {
    (void)in_sizes; (void)n_in; (void)out_size;
    // metadata order: times, codes, lengths, W_emb, b_emb, W_ode1..3, W_u, b_u,
    //                 W_ih, W_hh, b_ih, b_hh, W_d1, b_d1, W_d2, b_d2
    const float* codes   = (const float*)d_in[1];
    const int*   lengths = (const int*)d_in[2];     // dtype auto-detected in prep_len
    const float* W_emb   = (const float*)d_in[3];
    const float* b_emb   = (const float*)d_in[4];
    const float* W1      = (const float*)d_in[5];
    const float* W2      = (const float*)d_in[6];
    const float* W3      = (const float*)d_in[7];
    const float* W_u     = (const float*)d_in[8];
    const float* b_u     = (const float*)d_in[9];
    const float* W_ih    = (const float*)d_in[10];
    const float* W_hh    = (const float*)d_in[11];
    const float* b_ih    = (const float*)d_in[12];
    const float* b_hh    = (const float*)d_in[13];
    const float* W_d1    = (const float*)d_in[14];
    const float* b_d1    = (const float*)d_in[15];
    const float* W_d2    = (const float*)d_in[16];
    const float* b_d2    = (const float*)d_in[17];
    float* out = (float*)d_out;

    prep_len<<<2, 256>>>(lengths);
    prep_ode<<<(HP * HP + 255) / 256, 256>>>(W1, W2, W3);
    prep_misc<<<(HP * HP + 255) / 256, 256>>>(W_u, b_u, W_ih, W_hh, W_d1, b_d1);
    prep_wd2<<<(E_ * VP + 255) / 256, 256>>>(W_d2);
    prep_wemb<<<(V_ * E_ + 255) / 256, 256>>>(W_emb);

    embed_kernel<<<B_ * T_, 256>>>(codes, b_emb);
    seq_kernel<<<B_ / 4, HP>>>(b_ih, b_hh);
    d1_kernel<<<((T_ - 1) * B_) / 4, NP1>>>();

    dim3 lgrid(((T_ - 1) * B_) / 32, (V_ + 255) / 256);
    logits_kernel<<<lgrid, 256>>>(b_d2, out);
}

// round 11
// speedup vs baseline: 1.0102x; 1.0102x over previous
#include <cuda_runtime.h>
#include <math.h>

#define B_  512
#define T_  24
#define V_  8000
#define E_  300
#define M_  30
#define H_  330
#define HP  352            // padded H (11 warps)
#define KSPL 165           // split-K half for seq stages
#define NSTEPS 8
#define DT_ 0.875f         // 7/8
#define VP  8192           // padded V for W_d2T
#define NP1 320            // padded N for d1 stage

// ---------------- device scratch (static, no allocation) ----------------
__device__ float g_WodeT[3 * HP * HP];   // [which][k][n] k<330 real, zero-padded
__device__ float g_WuT[HP * HP];         // [k<330][n<300]
__device__ float g_WihT[E_ * 96];        // [e<300][g<90]
__device__ float g_WhhT[M_ * 96];        // [m<30][g<90]
__device__ float g_Wd1T[E_ * NP1];       // [k<300][n<300]
__device__ float g_Wd2T[E_ * VP];        // [n<300][v<8000]
__device__ float g_WembT[V_ * E_];       // [v][e]
__device__ float g_bu_pad[HP];
__device__ float g_bd1_pad[NP1];
__device__ int   g_len[B_];
__device__ float g_gall[(size_t)B_ * T_ * E_];        // [b][t][e]
__device__ float g_hemb[(size_t)(T_ - 1) * B_ * E_];  // [kk][b][e]
__device__ float g_d1[(size_t)(T_ - 1) * B_ * E_];    // [kk][b][e]

// ---------------- lengths normalization (int32 vs int64 auto-detect) ----------------
__global__ void prep_len(const int* __restrict__ Lraw) {
    int b = blockIdx.x * blockDim.x + threadIdx.x;
    if (b >= B_) return;
    int is64 = (Lraw[1] == 0);
    g_len[b] = is64 ? Lraw[2 * b] : Lraw[b];
}

// ---------------- weight prep ----------------
__global__ void prep_ode(const float* __restrict__ W1, const float* __restrict__ W2,
                         const float* __restrict__ W3) {
    int i = blockIdx.x * blockDim.x + threadIdx.x;
    if (i >= HP * HP) return;
    int k = i / HP, n = i % HP;
    float v1 = 0.f, v2 = 0.f, v3 = 0.f;
    if (k < H_ && n < H_) {
        v1 = W1[n * H_ + k];
        v2 = W2[n * H_ + k];
        v3 = W3[n * H_ + k];
    }
    g_WodeT[i] = v1;
    g_WodeT[HP * HP + i] = v2;
    g_WodeT[2 * HP * HP + i] = v3;
}

__global__ void prep_misc(const float* __restrict__ Wu,  const float* __restrict__ bu,
                          const float* __restrict__ Wih, const float* __restrict__ Whh,
                          const float* __restrict__ Wd1, const float* __restrict__ bd1) {
    int i = blockIdx.x * blockDim.x + threadIdx.x;
    if (i < HP * HP) {
        int k = i / HP, n = i % HP;
        g_WuT[i] = (k < H_ && n < E_) ? Wu[n * H_ + k] : 0.f;
    }
    if (i < E_ * 96) {
        int e = i / 96, g = i % 96;
        g_WihT[i] = (g < 90) ? Wih[g * E_ + e] : 0.f;
    }
    if (i < M_ * 96) {
        int m = i / 96, g = i % 96;
        g_WhhT[i] = (g < 90) ? Whh[g * M_ + m] : 0.f;
    }
    if (i < E_ * NP1) {
        int k = i / NP1, n = i % NP1;
        g_Wd1T[i] = (n < E_) ? Wd1[n * E_ + k] : 0.f;
    }
    if (i < HP)  g_bu_pad[i]  = (i < E_) ? bu[i]  : 0.f;
    if (i < NP1) g_bd1_pad[i] = (i < E_) ? bd1[i] : 0.f;
}

__global__ void prep_wd2(const float* __restrict__ Wd2) {
    int i = blockIdx.x * blockDim.x + threadIdx.x;
    if (i >= E_ * VP) return;
    int n = i / VP, v = i % VP;
    g_Wd2T[i] = (v < V_) ? Wd2[v * E_ + n] : 0.f;
}

__global__ void prep_wemb(const float* __restrict__ Wemb) {
    int i = blockIdx.x * blockDim.x + threadIdx.x;
    if (i >= V_ * E_) return;
    int v = i / E_, e = i % E_;
    g_WembT[i] = Wemb[e * V_ + v];
}

// ---------------- sparse embedding (deterministic prefix-scan compaction) ----------------
__global__ void __launch_bounds__(256) embed_kernel(const float* __restrict__ codes,
                                                    const float* __restrict__ bemb) {
    __shared__ int idx[1024];
    __shared__ int cnts[256];
    __shared__ int total;
    int blk = blockIdx.x;               // blk = b*T_ + t
    int t = threadIdx.x;
    const float* crow = codes + (size_t)blk * V_;
    int base = t * 32;
    int c = 0;
#pragma unroll 4
    for (int j = 0; j < 32; j++) {
        int v = base + j;
        if (v < V_ && crow[v] != 0.f) c++;
    }
    cnts[t] = c;
    __syncthreads();
    for (int off = 1; off < 256; off <<= 1) {
        int val = cnts[t];
        int add = (t >= off) ? cnts[t - off] : 0;
        __syncthreads();
        cnts[t] = val + add;
        __syncthreads();
    }
    int p = cnts[t] - c;
    for (int j = 0; j < 32; j++) {
        int v = base + j;
        if (v < V_ && crow[v] != 0.f) {
            if (p < 1024) idx[p] = v;
            p++;
        }
    }
    if (t == 255) total = cnts[255];
    __syncthreads();
    int n = total > 1024 ? 1024 : total;
    for (int e = t; e < E_; e += 256) {
        float acc = bemb[e];
        for (int j = 0; j < n; j++) acc += g_WembT[idx[j] * E_ + e];
        g_gall[(size_t)blk * E_ + e] = acc;
    }
}

// ---------------- sequential ODE + GRU kernel (704 threads, split-K(2)) ----------------
// Thread tid: kh = tid/352 (k-half), n = tid%352 (output column).
// Warps 0-10 are kh=0, warps 11-21 are kh=1 (no divergent warps).
template <bool TANH, bool BIAS>
__device__ __forceinline__ void mm2(const float* __restrict__ WT,
                                    const float4* __restrict__ xs,
                                    float4* __restrict__ ys,
                                    float4* __restrict__ part,
                                    const float* __restrict__ bias,
                                    int n, int kh) {
    float a0 = 0.f, a1 = 0.f, a2 = 0.f, a3 = 0.f;
    const float* wp = WT + kh * (KSPL * HP) + n;
    const float4* xp = xs + kh * KSPL;
#pragma unroll 5
    for (int k = 0; k < KSPL; k++) {
        float w = wp[k * HP];
        float4 x = xp[k];
        a0 = fmaf(w, x.x, a0);
        a1 = fmaf(w, x.y, a1);
        a2 = fmaf(w, x.z, a2);
        a3 = fmaf(w, x.w, a3);
    }
    if (kh) part[n] = make_float4(a0, a1, a2, a3);
    __syncthreads();
    if (!kh) {
        float4 p = part[n];
        a0 += p.x; a1 += p.y; a2 += p.z; a3 += p.w;
        if (BIAS) { float bv = bias[n]; a0 += bv; a1 += bv; a2 += bv; a3 += bv; }
        if (TANH) { a0 = tanhf(a0); a1 = tanhf(a1); a2 = tanhf(a2); a3 = tanhf(a3); }
        ys[n] = make_float4(a0, a1, a2, a3);
    }
    __syncthreads();
}

__device__ __forceinline__ void ode_f2(const float4* src, float4* bufA, float4* bufB,
                                       float4* part, int n, int kh) {
    mm2<true, false>(g_WodeT,               src,  bufA, part, nullptr, n, kh);  // W1
    mm2<true, false>(g_WodeT + HP * HP,     bufA, bufB, part, nullptr, n, kh);  // W2
    mm2<true, false>(g_WodeT + 2 * HP * HP, bufB, bufA, part, nullptr, n, kh);  // W3 -> bufA
}

__device__ __forceinline__ float sigf(float x) { return 1.f / (1.f + expf(-x)); }

__global__ void __launch_bounds__(2 * HP, 1) seq_kernel(const float* __restrict__ b_ih,
                                                        const float* __restrict__ b_hh) {
    __shared__ float4 Hs[HP], ACC[HP], Ys[HP], As[HP], Bs[HP], Ps[HP];
    __shared__ float4 G1[96], G2[96];
    int tid = threadIdx.x;
    int kh = tid >= HP;
    int n  = tid - kh * HP;
    int b0 = blockIdx.x * 4;

    // h0 = [zeros(M), g_all[:,0,:]]
    if (!kh) {
        float4 h = make_float4(0.f, 0.f, 0.f, 0.f);
        if (n >= M_ && n < H_) {
            int e = n - M_;
            h.x = g_gall[((size_t)(b0 + 0) * T_ + 0) * E_ + e];
            h.y = g_gall[((size_t)(b0 + 1) * T_ + 0) * E_ + e];
            h.z = g_gall[((size_t)(b0 + 2) * T_ + 0) * E_ + e];
            h.w = g_gall[((size_t)(b0 + 3) * T_ + 0) * E_ + e];
        }
        Hs[n] = h;
    }
    __syncthreads();

    for (int k = 1; k < T_; k++) {
        // ---- RK4 with N_STEPS substeps ----
        for (int s = 0; s < NSTEPS; s++) {
            ode_f2(Hs, As, Bs, Ps, n, kh);                       // k1 -> As
            if (!kh) {
                float4 a = As[n], h = Hs[n];
                ACC[n] = a;
                Ys[n] = make_float4(h.x + 0.5f * DT_ * a.x, h.y + 0.5f * DT_ * a.y,
                                    h.z + 0.5f * DT_ * a.z, h.w + 0.5f * DT_ * a.w);
            }
            __syncthreads();
            ode_f2(Ys, As, Bs, Ps, n, kh);                       // k2 -> As
            if (!kh) {
                float4 a = As[n], h = Hs[n], c = ACC[n];
                ACC[n] = make_float4(c.x + 2.f * a.x, c.y + 2.f * a.y,
                                     c.z + 2.f * a.z, c.w + 2.f * a.w);
                Ys[n] = make_float4(h.x + 0.5f * DT_ * a.x, h.y + 0.5f * DT_ * a.y,
                                    h.z + 0.5f * DT_ * a.z, h.w + 0.5f * DT_ * a.w);
            }
            __syncthreads();
            ode_f2(Ys, As, Bs, Ps, n, kh);                       // k3 -> As
            if (!kh) {
                float4 a = As[n], h = Hs[n], c = ACC[n];
                ACC[n] = make_float4(c.x + 2.f * a.x, c.y + 2.f * a.y,
                                     c.z + 2.f * a.z, c.w + 2.f * a.w);
                Ys[n] = make_float4(h.x + DT_ * a.x, h.y + DT_ * a.y,
                                    h.z + DT_ * a.z, h.w + DT_ * a.w);
            }
            __syncthreads();
            ode_f2(Ys, As, Bs, Ps, n, kh);                       // k4 -> As
            if (!kh) {
                const float c6 = DT_ / 6.f;
                float4 a = As[n], h = Hs[n], c = ACC[n];
                Hs[n] = make_float4(h.x + c6 * (c.x + a.x), h.y + c6 * (c.y + a.y),
                                    h.z + c6 * (c.z + a.z), h.w + c6 * (c.w + a.w));
            }
            __syncthreads();
        }

        // ---- dump h_emb for the decoupled decoder; build cin = [h_mem, g_k] ----
        if (!kh) {
            if (n < E_) {
                float4 v = Hs[M_ + n];
                size_t base = ((size_t)(k - 1) * B_ + b0) * E_ + n;
                g_hemb[base]          = v.x;
                g_hemb[base + E_]     = v.y;
                g_hemb[base + 2 * E_] = v.z;
                g_hemb[base + 3 * E_] = v.w;
            }
            float4 c = make_float4(0.f, 0.f, 0.f, 0.f);
            if (n < M_) c = Hs[n];
            else if (n < H_) {
                int e = n - M_;
                c.x = g_gall[((size_t)(b0 + 0) * T_ + k) * E_ + e];
                c.y = g_gall[((size_t)(b0 + 1) * T_ + k) * E_ + e];
                c.z = g_gall[((size_t)(b0 + 2) * T_ + k) * E_ + e];
                c.w = g_gall[((size_t)(b0 + 3) * T_ + k) * E_ + e];
            }
            Ys[n] = c;
        }
        __syncthreads();

        // ---- x = cin @ W_u^T + b_u  -> As ----
        mm2<false, true>(g_WuT, Ys, As, Ps, g_bu_pad, n, kh);

        // ---- GRU gates (runs on low warps; all gate inputs ready after mm2 barrier) ----
        if (tid < 96) {
            int g = tid;
            float bb = (g < 90) ? b_ih[g] : 0.f;
            float4 a = make_float4(bb, bb, bb, bb);
#pragma unroll 4
            for (int e = 0; e < E_; e++) {
                float w = g_WihT[e * 96 + g];
                float4 x = As[e];
                a.x = fmaf(w, x.x, a.x); a.y = fmaf(w, x.y, a.y);
                a.z = fmaf(w, x.z, a.z); a.w = fmaf(w, x.w, a.w);
            }
            G1[g] = a;
        } else if (tid < 192) {
            int g = tid - 96;
            float bb = (g < 90) ? b_hh[g] : 0.f;
            float4 a = make_float4(bb, bb, bb, bb);
#pragma unroll
            for (int m = 0; m < M_; m++) {
                float w = g_WhhT[m * 96 + g];
                float4 x = Hs[m];
                a.x = fmaf(w, x.x, a.x); a.y = fmaf(w, x.y, a.y);
                a.z = fmaf(w, x.z, a.z); a.w = fmaf(w, x.w, a.w);
            }
            G2[g] = a;
        }
        __syncthreads();

        if (tid < M_) {
            int m = tid;
            float4 xr = G1[m],          hr = G2[m];
            float4 xz = G1[M_ + m],     hz = G2[M_ + m];
            float4 xn = G1[2 * M_ + m], hn = G2[2 * M_ + m];
            float4 ho = Hs[m];
            float4 hnew;
            {
                float r = sigf(xr.x + hr.x), z = sigf(xz.x + hz.x);
                float t = tanhf(xn.x + r * hn.x);
                hnew.x = (1.f - z) * t + z * ho.x;
            }
            {
                float r = sigf(xr.y + hr.y), z = sigf(xz.y + hz.y);
                float t = tanhf(xn.y + r * hn.y);
                hnew.y = (1.f - z) * t + z * ho.y;
            }
            {
                float r = sigf(xr.z + hr.z), z = sigf(xz.z + hz.z);
                float t = tanhf(xn.z + r * hn.z);
                hnew.z = (1.f - z) * t + z * ho.z;
            }
            {
                float r = sigf(xr.w + hr.w), z = sigf(xz.w + hz.w);
                float t = tanhf(xn.w + r * hn.w);
                hnew.w = (1.f - z) * t + z * ho.w;
            }
            Hs[m] = hnew;
        }
        __syncthreads();
    }
}

// ---------------- decoder stage 1: d1 = leaky_relu(hemb @ W_d1^T + b_d1) ----------------
__global__ void __launch_bounds__(NP1) d1_kernel() {
    __shared__ float4 Xs[E_];
    int tid = threadIdx.x;
    int i0 = blockIdx.x * 4;
    if (tid < E_) {
        float4 v;
        v.x = g_hemb[(size_t)(i0 + 0) * E_ + tid];
        v.y = g_hemb[(size_t)(i0 + 1) * E_ + tid];
        v.z = g_hemb[(size_t)(i0 + 2) * E_ + tid];
        v.w = g_hemb[(size_t)(i0 + 3) * E_ + tid];
        Xs[tid] = v;
    }
    __syncthreads();
    int n = tid;
    float bv = g_bd1_pad[n];
    float a0 = bv, a1 = bv, a2 = bv, a3 = bv;
#pragma unroll 5
    for (int kk = 0; kk < E_; kk++) {
        float w = g_Wd1T[kk * NP1 + n];
        float4 x = Xs[kk];
        a0 = fmaf(w, x.x, a0); a1 = fmaf(w, x.y, a1);
        a2 = fmaf(w, x.z, a2); a3 = fmaf(w, x.w, a3);
    }
    a0 = a0 >= 0.f ? a0 : 0.01f * a0;
    a1 = a1 >= 0.f ? a1 : 0.01f * a1;
    a2 = a2 >= 0.f ? a2 : 0.01f * a2;
    a3 = a3 >= 0.f ? a3 : 0.01f * a3;
    if (n < E_) {
        g_d1[(size_t)(i0 + 0) * E_ + n] = a0;
        g_d1[(size_t)(i0 + 1) * E_ + n] = a1;
        g_d1[(size_t)(i0 + 2) * E_ + n] = a2;
        g_d1[(size_t)(i0 + 3) * E_ + n] = a3;
    }
}

// ---------------- decoder stage 2: logits = d1 @ W_d2^T + b_d2 (masked) ----------------
#define AS4 9   // A_s row stride in float4 (36 floats)
__global__ void __launch_bounds__(256) logits_kernel(const float* __restrict__ bd2,
                                                     float* __restrict__ out) {
    __shared__ float4 A_s4[E_ * AS4];
    __shared__ int vld[32];
    float* A_s = (float*)A_s4;
    int tid = threadIdx.x;
    int i0 = blockIdx.x * 32;                 // row tile (i = kk*512 + b)
    int vt = blockIdx.y * 256;                // v tile

    if (tid < 32) {
        int i = i0 + tid;
        int kk = i >> 9, b = i & 511;
        vld[tid] = ((kk + 1) < g_len[b]) ? 1 : 0;
    }
    int any = __syncthreads_or(
        tid < 32 ? ((((i0 + tid) >> 9) + 1) < g_len[(i0 + tid) & 511]) : 0);

    int vq = vt + (tid & 63) * 4;
    int g2 = (tid >> 6) * 2;                  // float4 offset within A_s row
    int rb = (tid >> 6) * 8;                  // first of 8 rows this thread owns
    float4 acc[8];
#pragma unroll
    for (int r = 0; r < 8; r++) acc[r] = make_float4(0.f, 0.f, 0.f, 0.f);

    if (any) {
        for (int idx = tid; idx < 32 * E_; idx += 256) {
            int r = idx / E_, kk = idx - r * E_;
            A_s[kk * 36 + r] = g_d1[(size_t)(i0 + r) * E_ + kk];
        }
        __syncthreads();
        if (vq < V_) {
#pragma unroll 2
            for (int kk = 0; kk < E_; kk++) {
                float4 w = *(const float4*)&g_Wd2T[(size_t)kk * VP + vq];
                float4 xa = A_s4[kk * AS4 + g2];
                float4 xb = A_s4[kk * AS4 + g2 + 1];
                float ar[8] = {xa.x, xa.y, xa.z, xa.w, xb.x, xb.y, xb.z, xb.w};
#pragma unroll
                for (int r = 0; r < 8; r++) {
                    acc[r].x = fmaf(ar[r], w.x, acc[r].x);
                    acc[r].y = fmaf(ar[r], w.y, acc[r].y);
                    acc[r].z = fmaf(ar[r], w.z, acc[r].z);
                    acc[r].w = fmaf(ar[r], w.w, acc[r].w);
                }
            }
        }
    }

    if (vq < V_) {
        float4 bb = *(const float4*)&bd2[vq];
        const float4 zero = make_float4(0.f, 0.f, 0.f, 0.f);
#pragma unroll
        for (int r = 0; r < 8; r++) {
            int i = i0 + rb + r;
            int kk = i >> 9, b = i & 511;
            float4 o;
            if (vld[rb + r]) {
                o = make_float4(acc[r].x + bb.x, acc[r].y + bb.y,
                                acc[r].z + bb.z, acc[r].w + bb.w);
            } else {
                o = zero;
            }
            *(float4*)&out[((size_t)b * (T_ - 1) + kk) * V_ + vq] = o;
        }
    }
}

// ---------------- launch ----------------
extern "C" void kernel_launch(void* const* d_in, const int* in_sizes, int n_in,
                              void* d_out, int out_size) {
    (void)in_sizes; (void)n_in; (void)out_size;
    const float* codes   = (const float*)d_in[1];
    const int*   lengths = (const int*)d_in[2];     // dtype auto-detected in prep_len
    const float* W_emb   = (const float*)d_in[3];
    const float* b_emb   = (const float*)d_in[4];
    const float* W1      = (const float*)d_in[5];
    const float* W2      = (const float*)d_in[6];
    const float* W3      = (const float*)d_in[7];
    const float* W_u     = (const float*)d_in[8];
    const float* b_u     = (const float*)d_in[9];
    const float* W_ih    = (const float*)d_in[10];
    const float* W_hh    = (const float*)d_in[11];
    const float* b_ih    = (const float*)d_in[12];
    const float* b_hh    = (const float*)d_in[13];
    const float* W_d1    = (const float*)d_in[14];
    const float* b_d1    = (const float*)d_in[15];
    const float* W_d2    = (const float*)d_in[16];
    const float* b_d2    = (const float*)d_in[17];
    float* out = (float*)d_out;

    // Launch order arranged so ncu (-s 5 -c 1) captures seq_kernel (launch #6).
    prep_wemb<<<(V_ * E_ + 255) / 256, 256>>>(W_emb);                       // 1
    prep_ode<<<(HP * HP + 255) / 256, 256>>>(W1, W2, W3);                   // 2
    prep_misc<<<(HP * HP + 255) / 256, 256>>>(W_u, b_u, W_ih, W_hh, W_d1, b_d1); // 3
    prep_wd2<<<(E_ * VP + 255) / 256, 256>>>(W_d2);                         // 4
    embed_kernel<<<B_ * T_, 256>>>(codes, b_emb);                           // 5
    seq_kernel<<<B_ / 4, 2 * HP>>>(b_ih, b_hh);                             // 6 <- profiled
    prep_len<<<2, 256>>>(lengths);                                          // 7
    d1_kernel<<<((T_ - 1) * B_) / 4, NP1>>>();                              // 8
    dim3 lgrid(((T_ - 1) * B_) / 32, (V_ + 255) / 256);
    logits_kernel<<<lgrid, 256>>>(b_d2, out);                               // 9
}